// round 10
// baseline (speedup 1.0000x reference)
#include <cuda_runtime.h>

// ManualGRU: B=256, S=2048, I=64, H=128
// out = [hidden_seq (B,S,H) fp32][h_last (B,H) fp32]

#define BB   256
#define SS   2048
#define II   64
#define HH   128
#define G3   384      // 3*H

// Scratch: from_input laid out as [s][b][384] so the scan reads coalesced rows.
__device__ float g_xin[(size_t)SS * BB * G3];

// ---------------- packed f32x2 helpers ----------------
__device__ __forceinline__ unsigned long long pk2(float lo, float hi) {
    unsigned long long r;
    asm("mov.b64 %0, {%1, %2};" : "=l"(r)
        : "r"(__float_as_uint(lo)), "r"(__float_as_uint(hi)));
    return r;
}
__device__ __forceinline__ unsigned long long f2fma(unsigned long long a,
                                                    unsigned long long b,
                                                    unsigned long long c) {
    unsigned long long d;
    asm("fma.rn.f32x2 %0, %1, %2, %3;" : "=l"(d) : "l"(a), "l"(b), "l"(c));
    return d;
}
__device__ __forceinline__ float psum2(unsigned long long p) {
    unsigned int lo, hi;
    asm("mov.b64 {%0, %1}, %2;" : "=r"(lo), "=r"(hi) : "l"(p));
    return __uint_as_float(lo) + __uint_as_float(hi);
}
__device__ __forceinline__ void unpk2(unsigned long long p, float& a, float& b) {
    unsigned int lo, hi;
    asm("mov.b64 {%0, %1}, %2;" : "=r"(lo), "=r"(hi) : "l"(p));
    a = __uint_as_float(lo); b = __uint_as_float(hi);
}

__device__ __forceinline__ float fast_sigmoid(float x) {
    float e = __expf(-x);
    return __fdividef(1.0f, 1.0f + e);
}
__device__ __forceinline__ float fast_tanh(float x) {
    float ax = fabsf(x);
    float e  = __expf(-2.0f * ax);
    float t  = __fdividef(1.0f - e, 1.0f + e);
    return copysignf(t, x);
}

// ---------------------------------------------------------------------------
// Phase 1: from_input = inputs @ W_in + b_in
// 128 rows/block, 3 col-chunks of 128, 256 threads, 8x8 thread tiles.
// A tile stored pre-duplicated as f32x2 (u64) with padded stride -> broadcast
// LDS.64, zero pack movs. W chunk read as LDS.128 col-pairs.
// ---------------------------------------------------------------------------
#define AS2_STRIDE 65                    // u64 per row (64 + 1 pad)
#define SMEM_GEMM  (128 * AS2_STRIDE * 8 + 64 * 128 * 4)   // 99328 B

extern __shared__ unsigned long long dyn_smem[];

__global__ void __launch_bounds__(256, 2)
k_in_gemm(const float* __restrict__ X, const float* __restrict__ W,
          const float* __restrict__ bias) {
    unsigned long long* As2 = dyn_smem;                       // [128][65] u64 dup
    float*              Ws  = (float*)(dyn_smem + 128 * AS2_STRIDE); // [64][128]

    const int tid  = threadIdx.x;
    const int row0 = blockIdx.x * 128;
    const int bb   = row0 >> 11;
    const int s0   = row0 & 2047;

    // Load A tile (128x64) and duplicate each value into both f32x2 lanes.
    {
        const float4* Xv = (const float4*)(X + (size_t)row0 * II);
#pragma unroll
        for (int i = 0; i < 8; i++) {
            int fi  = tid + 256 * i;       // float4 index 0..2047
            float4 v = Xv[fi];
            int row = fi >> 4;             // 16 float4 per 64-float row
            int k4  = (fi & 15) * 4;
            unsigned long long* dst = &As2[row * AS2_STRIDE + k4];
            dst[0] = pk2(v.x, v.x);
            dst[1] = pk2(v.y, v.y);
            dst[2] = pk2(v.z, v.z);
            dst[3] = pk2(v.w, v.w);
        }
    }

    const int tx = tid & 15;   // cols: tx*4..+3 and 64+tx*4..+3
    const int ty = tid >> 4;   // rows: ty*8..+7

    for (int cc = 0; cc < 3; cc++) {
        __syncthreads();
        // Load W chunk [64 k][128 cols]
#pragma unroll
        for (int i = 0; i < 8; i++) {
            int fi = tid + 256 * i;        // 2048 float4
            int k  = fi >> 5;              // 32 float4 per 128-col row
            int c  = (fi & 31) * 4;
            *(float4*)&Ws[k * 128 + c] =
                *(const float4*)&W[(size_t)k * G3 + cc * 128 + c];
        }
        __syncthreads();

        unsigned long long acc[8][4];
#pragma unroll
        for (int r = 0; r < 8; r++)
#pragma unroll
            for (int c = 0; c < 4; c++) acc[r][c] = 0ull;

#pragma unroll 8
        for (int k = 0; k < 64; k++) {
            ulonglong2 w01 = *(const ulonglong2*)&Ws[k * 128 + tx * 4];
            ulonglong2 w23 = *(const ulonglong2*)&Ws[k * 128 + 64 + tx * 4];
#pragma unroll
            for (int r = 0; r < 8; r++) {
                unsigned long long a = As2[(ty * 8 + r) * AS2_STRIDE + k];
                acc[r][0] = f2fma(a, w01.x, acc[r][0]);
                acc[r][1] = f2fma(a, w01.y, acc[r][1]);
                acc[r][2] = f2fma(a, w23.x, acc[r][2]);
                acc[r][3] = f2fma(a, w23.y, acc[r][3]);
            }
        }

        const int cb0 = cc * 128 + tx * 4;
        const int cb1 = cb0 + 64;
        const float4 bi0 = *(const float4*)&bias[cb0];
        const float4 bi1 = *(const float4*)&bias[cb1];
#pragma unroll
        for (int r = 0; r < 8; r++) {
            float4 o0, o1;
            unpk2(acc[r][0], o0.x, o0.y);
            unpk2(acc[r][1], o0.z, o0.w);
            unpk2(acc[r][2], o1.x, o1.y);
            unpk2(acc[r][3], o1.z, o1.w);
            o0.x += bi0.x; o0.y += bi0.y; o0.z += bi0.z; o0.w += bi0.w;
            o1.x += bi1.x; o1.y += bi1.y; o1.z += bi1.z; o1.w += bi1.w;
            int s = s0 + ty * 8 + r;
            float* orow = &g_xin[((size_t)s * BB + bb) * G3];
            *(float4*)&orow[cb0] = o0;
            *(float4*)&orow[cb1] = o1;
        }
    }
}

// ---------------------------------------------------------------------------
// Phase 2: GRU scan, two-phase batch-pipelined.
// 128 CTAs x 384 threads, 2 independent batch recurrences per CTA.
// Phase A of step t:  gate-update(b1, t-1)  ||  matvec(b0, t)   -> barrier
// Phase B of step t:  gate-update(b0, t)    ||  matvec(b1, t)   -> barrier
// Gate latency chain overlaps the other batch's matvec issue.
// Thread t: cg = t%96 owns cols 4cg..4cg+3, kg = t/96 owns k-slice 32kg..+31.
// Gate work embedded in threads 256..383 (j = t-256).
// ---------------------------------------------------------------------------
__global__ void __launch_bounds__(384, 1)
k_gru(const float* __restrict__ Wh, const float* __restrict__ bias,
      float* __restrict__ out) {
    __shared__ __align__(16) float h_sm[2][HH];        // 1 KB
    __shared__ __align__(16) float part[2][4][G3];     // 12 KB  [b][kg][col]

    const int t  = threadIdx.x;
    const int b0 = blockIdx.x * 2;
    const int cg = t % 96;
    const int kg = t / 96;            // 0..3 (uniform per warp: 96 % 32 == 0)
    const int col0 = 4 * cg;
    const int k0   = 32 * kg;

    // Register-resident weight slice: wreg[c][i] = {Wh[k0+2i][col0+c], Wh[k0+2i+1][col0+c]}
    unsigned long long wreg[4][16];
#pragma unroll
    for (int i = 0; i < 16; i++) {
        const float* r0 = Wh + (size_t)(k0 + 2 * i) * G3 + col0;
        const float* r1 = r0 + G3;
#pragma unroll
        for (int c = 0; c < 4; c++) wreg[c][i] = pk2(r0[c], r1[c]);
    }

    // Gate-thread state
    const int j = t - 256;            // valid when t >= 256
    float bhr = 0.f, bhz = 0.f, bhn = 0.f;
    float xr0 = 0.f, xz0 = 0.f, xn0 = 0.f;   // x(b0, st)        entering iter st
    float xr1 = 0.f, xz1 = 0.f, xn1 = 0.f;   // x(b1, st-1)      entering iter st
    if (t >= 256) {
        bhr = bias[G3 + j];
        bhz = bias[G3 + 128 + j];
        bhn = bias[G3 + 256 + j];
        const float* xb = g_xin + (size_t)b0 * G3;   // step 0, batch b0
        xr0 = xb[j]; xz0 = xb[128 + j]; xn0 = xb[256 + j];
    }

    if (t < HH) { h_sm[0][t] = 0.0f; h_sm[1][t] = 0.0f; }
    __syncthreads();

#define MATVEC(bsel)                                                          \
    {                                                                         \
        unsigned long long a0 = 0ull, a1 = 0ull, a2 = 0ull, a3 = 0ull;        \
        const ulonglong2* hv = (const ulonglong2*)&h_sm[bsel][k0];            \
        _Pragma("unroll")                                                     \
        for (int q = 0; q < 8; q++) {                                         \
            ulonglong2 hq = hv[q];                                            \
            a0 = f2fma(wreg[0][2 * q],     hq.x, a0);                         \
            a0 = f2fma(wreg[0][2 * q + 1], hq.y, a0);                         \
            a1 = f2fma(wreg[1][2 * q],     hq.x, a1);                         \
            a1 = f2fma(wreg[1][2 * q + 1], hq.y, a1);                         \
            a2 = f2fma(wreg[2][2 * q],     hq.x, a2);                         \
            a2 = f2fma(wreg[2][2 * q + 1], hq.y, a2);                         \
            a3 = f2fma(wreg[3][2 * q],     hq.x, a3);                         \
            a3 = f2fma(wreg[3][2 * q + 1], hq.y, a3);                         \
        }                                                                     \
        float4 p;                                                             \
        p.x = psum2(a0); p.y = psum2(a1); p.z = psum2(a2); p.w = psum2(a3);   \
        *(float4*)&part[bsel][kg][col0] = p;                                  \
    }

#define GATE(bsel, step, xr, xz, xn)                                          \
    {                                                                         \
        float vr = part[bsel][0][j]       + part[bsel][1][j]                  \
                 + part[bsel][2][j]       + part[bsel][3][j]       + bhr;     \
        float vz = part[bsel][0][128 + j] + part[bsel][1][128 + j]            \
                 + part[bsel][2][128 + j] + part[bsel][3][128 + j] + bhz;     \
        float vn = part[bsel][0][256 + j] + part[bsel][1][256 + j]            \
                 + part[bsel][2][256 + j] + part[bsel][3][256 + j] + bhn;     \
        float rr = fast_sigmoid((xr) + vr);                                   \
        float zz = fast_sigmoid((xz) + vz);                                   \
        float nn = fast_tanh((xn) + rr * vn);                                 \
        float ho = h_sm[bsel][j];                                             \
        float hn = nn + zz * (ho - nn);                                       \
        h_sm[bsel][j] = hn;                                                   \
        out[((size_t)(b0 + (bsel)) * SS + (step)) * HH + j] = hn;             \
    }

    for (int st = 0; st < SS; st++) {
        // ---------- Phase A: gate(b1, st-1) || matvec(b0, st) ----------
        float pr1 = 0.f, pz1 = 0.f, pn1 = 0.f;
        if (t >= 256) {
            // prefetch x(b1, st) (consumed at phase A of st+1 / epilogue)
            const float* xb = g_xin + ((size_t)st * BB + b0 + 1) * G3;
            pr1 = xb[j]; pz1 = xb[128 + j]; pn1 = xb[256 + j];
            if (st > 0) GATE(1, st - 1, xr1, xz1, xn1);
        }
        MATVEC(0);
        xr1 = pr1; xz1 = pz1; xn1 = pn1;
        __syncthreads();

        // ---------- Phase B: gate(b0, st) || matvec(b1, st) ----------
        float pr0 = 0.f, pz0 = 0.f, pn0 = 0.f;
        if (t >= 256) {
            if (st + 1 < SS) {   // prefetch x(b0, st+1)
                const float* xb = g_xin + ((size_t)(st + 1) * BB + b0) * G3;
                pr0 = xb[j]; pz0 = xb[128 + j]; pn0 = xb[256 + j];
            }
            GATE(0, st, xr0, xz0, xn0);
        }
        MATVEC(1);
        xr0 = pr0; xz0 = pz0; xn0 = pn0;
        __syncthreads();
    }

    // Epilogue: gate(b1, SS-1); xr1 holds x(b1, SS-1)
    if (t >= 256) GATE(1, SS - 1, xr1, xz1, xn1);
    __syncthreads();

    // h_last
    if (t < HH) {
        const size_t off = (size_t)BB * SS * HH;
        out[off + (size_t)b0 * HH + t]       = h_sm[0][t];
        out[off + (size_t)(b0 + 1) * HH + t] = h_sm[1][t];
    }
#undef MATVEC
#undef GATE
}

// ---------------------------------------------------------------------------
extern "C" void kernel_launch(void* const* d_in, const int* in_sizes, int n_in,
                              void* d_out, int out_size) {
    (void)in_sizes; (void)n_in; (void)out_size;
    const float* X    = (const float*)d_in[0];   // inputs (B,S,I)
    const float* Win  = (const float*)d_in[1];   // W_in (I, 3H)
    const float* Wh   = (const float*)d_in[2];   // W_h  (H, 3H)
    const float* bias = (const float*)d_in[3];   // (6H,)
    float* out = (float*)d_out;

    // Idempotent; takes effect on the pre-capture correctness call.
    cudaFuncSetAttribute(k_in_gemm,
                         cudaFuncAttributeMaxDynamicSharedMemorySize, SMEM_GEMM);

    k_in_gemm<<<(BB * SS) / 128, 256, SMEM_GEMM>>>(X, Win, bias);
    k_gru<<<BB / 2, 384>>>(Wh, bias, out);
}

// round 11
// speedup vs baseline: 1.0795x; 1.0795x over previous
#include <cuda_runtime.h>

// ManualGRU: B=256, S=2048, I=64, H=128
// out = [hidden_seq (B,S,H) fp32][h_last (B,H) fp32]

#define BB   256
#define SS   2048
#define II   64
#define HH   128
#define G3   384      // 3*H

// Scratch: from_input laid out as [s][b][384] so the scan reads coalesced rows.
__device__ float g_xin[(size_t)SS * BB * G3];

// ---------------- packed f32x2 helpers ----------------
__device__ __forceinline__ unsigned long long pk2(float lo, float hi) {
    unsigned long long r;
    asm("mov.b64 %0, {%1, %2};" : "=l"(r)
        : "r"(__float_as_uint(lo)), "r"(__float_as_uint(hi)));
    return r;
}
__device__ __forceinline__ unsigned long long f2fma(unsigned long long a,
                                                    unsigned long long b,
                                                    unsigned long long c) {
    unsigned long long d;
    asm("fma.rn.f32x2 %0, %1, %2, %3;" : "=l"(d) : "l"(a), "l"(b), "l"(c));
    return d;
}
__device__ __forceinline__ unsigned long long f2add(unsigned long long a,
                                                    unsigned long long b) {
    unsigned long long d;
    asm("add.rn.f32x2 %0, %1, %2;" : "=l"(d) : "l"(a), "l"(b));
    return d;
}
__device__ __forceinline__ float psum2(unsigned long long p) {
    unsigned int lo, hi;
    asm("mov.b64 {%0, %1}, %2;" : "=r"(lo), "=r"(hi) : "l"(p));
    return __uint_as_float(lo) + __uint_as_float(hi);
}
__device__ __forceinline__ void unpk2(unsigned long long p, float& a, float& b) {
    unsigned int lo, hi;
    asm("mov.b64 {%0, %1}, %2;" : "=r"(lo), "=r"(hi) : "l"(p));
    a = __uint_as_float(lo); b = __uint_as_float(hi);
}

__device__ __forceinline__ float fast_sigmoid(float x) {
    float e = __expf(-x);
    return __fdividef(1.0f, 1.0f + e);
}
__device__ __forceinline__ float fast_tanh(float x) {
    float ax = fabsf(x);
    float e  = __expf(-2.0f * ax);
    float t  = __fdividef(1.0f - e, 1.0f + e);
    return copysignf(t, x);
}

// ---------------------------------------------------------------------------
// Phase 1: from_input = inputs @ W_in + b_in   (R10 version — measured ~545us)
// 128 rows/block, 3 col-chunks of 128, 256 threads, 8x8 thread tiles.
// A tile stored pre-duplicated as f32x2 (u64), padded stride -> LDS.64
// broadcast, zero pack movs. W chunk read as LDS.128 col-pairs.
// ---------------------------------------------------------------------------
#define AS2_STRIDE 65                    // u64 per row (64 + 1 pad)
#define SMEM_GEMM  (128 * AS2_STRIDE * 8 + 64 * 128 * 4)   // 99328 B

extern __shared__ unsigned long long dyn_smem[];

__global__ void __launch_bounds__(256, 2)
k_in_gemm(const float* __restrict__ X, const float* __restrict__ W,
          const float* __restrict__ bias) {
    unsigned long long* As2 = dyn_smem;                       // [128][65] u64 dup
    float*              Ws  = (float*)(dyn_smem + 128 * AS2_STRIDE); // [64][128]

    const int tid  = threadIdx.x;
    const int row0 = blockIdx.x * 128;
    const int bb   = row0 >> 11;
    const int s0   = row0 & 2047;

    {
        const float4* Xv = (const float4*)(X + (size_t)row0 * II);
#pragma unroll
        for (int i = 0; i < 8; i++) {
            int fi  = tid + 256 * i;
            float4 v = Xv[fi];
            int row = fi >> 4;
            int k4  = (fi & 15) * 4;
            unsigned long long* dst = &As2[row * AS2_STRIDE + k4];
            dst[0] = pk2(v.x, v.x);
            dst[1] = pk2(v.y, v.y);
            dst[2] = pk2(v.z, v.z);
            dst[3] = pk2(v.w, v.w);
        }
    }

    const int tx = tid & 15;
    const int ty = tid >> 4;

    for (int cc = 0; cc < 3; cc++) {
        __syncthreads();
#pragma unroll
        for (int i = 0; i < 8; i++) {
            int fi = tid + 256 * i;
            int k  = fi >> 5;
            int c  = (fi & 31) * 4;
            *(float4*)&Ws[k * 128 + c] =
                *(const float4*)&W[(size_t)k * G3 + cc * 128 + c];
        }
        __syncthreads();

        unsigned long long acc[8][4];
#pragma unroll
        for (int r = 0; r < 8; r++)
#pragma unroll
            for (int c = 0; c < 4; c++) acc[r][c] = 0ull;

#pragma unroll 8
        for (int k = 0; k < 64; k++) {
            ulonglong2 w01 = *(const ulonglong2*)&Ws[k * 128 + tx * 4];
            ulonglong2 w23 = *(const ulonglong2*)&Ws[k * 128 + 64 + tx * 4];
#pragma unroll
            for (int r = 0; r < 8; r++) {
                unsigned long long a = As2[(ty * 8 + r) * AS2_STRIDE + k];
                acc[r][0] = f2fma(a, w01.x, acc[r][0]);
                acc[r][1] = f2fma(a, w01.y, acc[r][1]);
                acc[r][2] = f2fma(a, w23.x, acc[r][2]);
                acc[r][3] = f2fma(a, w23.y, acc[r][3]);
            }
        }

        const int cb0 = cc * 128 + tx * 4;
        const int cb1 = cb0 + 64;
        const float4 bi0 = *(const float4*)&bias[cb0];
        const float4 bi1 = *(const float4*)&bias[cb1];
#pragma unroll
        for (int r = 0; r < 8; r++) {
            float4 o0, o1;
            unpk2(acc[r][0], o0.x, o0.y);
            unpk2(acc[r][1], o0.z, o0.w);
            unpk2(acc[r][2], o1.x, o1.y);
            unpk2(acc[r][3], o1.z, o1.w);
            o0.x += bi0.x; o0.y += bi0.y; o0.z += bi0.z; o0.w += bi0.w;
            o1.x += bi1.x; o1.y += bi1.y; o1.z += bi1.z; o1.w += bi1.w;
            int s = s0 + ty * 8 + r;
            float* orow = &g_xin[((size_t)s * BB + bb) * G3];
            *(float4*)&orow[cb0] = o0;
            *(float4*)&orow[cb1] = o1;
        }
    }
}

// ---------------------------------------------------------------------------
// Phase 2: GRU scan (R6 single-phase structure + packed partials + 8-warp gates)
// 128 CTAs x 384 threads, 2 batches per CTA, k-split matvec:
//   thread t: cg=t%96 owns cols 4cg..4cg+3, kg=t/96 owns k-slice 32kg..32kg+31
// Matvec partials stored PACKED (f32x2) -> no psum in matvec threads.
// Gates: threads 128..255 -> batch 0, threads 256..383 -> batch 1 (j = t%128).
// ---------------------------------------------------------------------------
__global__ void __launch_bounds__(384, 1)
k_gru(const float* __restrict__ Wh, const float* __restrict__ bias,
      float* __restrict__ out) {
    __shared__ __align__(16) float h_sm[2][HH];                          // 1 KB
    __shared__ __align__(16) unsigned long long part2[4][2][G3];         // 24 KB

    const int t  = threadIdx.x;
    const int b0 = blockIdx.x * 2;
    const int cg = t % 96;
    const int kg = t / 96;            // 0..3 (uniform per warp)
    const int col0 = 4 * cg;
    const int k0   = 32 * kg;

    // Register-resident weights: wreg[c][i] = {Wh[k0+2i][col0+c], Wh[k0+2i+1][col0+c]}
    unsigned long long wreg[4][16];
#pragma unroll
    for (int i = 0; i < 16; i++) {
        const float* r0 = Wh + (size_t)(k0 + 2 * i) * G3 + col0;
        const float* r1 = r0 + G3;
#pragma unroll
        for (int c = 0; c < 4; c++) wreg[c][i] = pk2(r0[c], r1[c]);
    }

    // Gate-thread state: threads 128..383; gb = batch select, j = column
    const int is_gate = (t >= 128);
    const int gb = (t >= 256) ? 1 : 0;
    const int j  = t & 127;
    float bhr = 0.f, bhz = 0.f, bhn = 0.f;
    float xrc = 0.f, xzc = 0.f, xnc = 0.f;     // x(b0+gb, st) entering iter st
    if (is_gate) {
        bhr = bias[G3 + j];
        bhz = bias[G3 + 128 + j];
        bhn = bias[G3 + 256 + j];
        const float* xb = g_xin + (size_t)(b0 + gb) * G3;   // step 0
        xrc = xb[j]; xzc = xb[128 + j]; xnc = xb[256 + j];
    }

    if (t < HH) { h_sm[0][t] = 0.0f; h_sm[1][t] = 0.0f; }
    __syncthreads();

    for (int st = 0; st < SS; st++) {
        // Prefetch next step's x (gate threads only; consumed next iteration)
        float xrp = 0.f, xzp = 0.f, xnp = 0.f;
        if (is_gate && st + 1 < SS) {
            const float* xb = g_xin + ((size_t)(st + 1) * BB + b0 + gb) * G3;
            xrp = xb[j]; xzp = xb[128 + j]; xnp = xb[256 + j];
        }

        // ---- matvec partials: 4 cols x 2 batches over k-slice [k0,k0+32) ----
        unsigned long long acc[4][2];
#pragma unroll
        for (int c = 0; c < 4; c++) { acc[c][0] = 0ull; acc[c][1] = 0ull; }

        const ulonglong2* hv0 = (const ulonglong2*)&h_sm[0][k0];
        const ulonglong2* hv1 = (const ulonglong2*)&h_sm[1][k0];
#pragma unroll
        for (int q = 0; q < 8; q++) {
            ulonglong2 a = hv0[q];
            ulonglong2 b = hv1[q];
#pragma unroll
            for (int c = 0; c < 4; c++) {
                acc[c][0] = f2fma(wreg[c][2 * q],     a.x, acc[c][0]);
                acc[c][0] = f2fma(wreg[c][2 * q + 1], a.y, acc[c][0]);
                acc[c][1] = f2fma(wreg[c][2 * q],     b.x, acc[c][1]);
                acc[c][1] = f2fma(wreg[c][2 * q + 1], b.y, acc[c][1]);
            }
        }
        // Store packed partials (no lane-sum here): 2x STS.128 per batch
        {
            ulonglong2 p;
            p.x = acc[0][0]; p.y = acc[1][0];
            *(ulonglong2*)&part2[kg][0][col0] = p;
            p.x = acc[2][0]; p.y = acc[3][0];
            *(ulonglong2*)&part2[kg][0][col0 + 2] = p;
            p.x = acc[0][1]; p.y = acc[1][1];
            *(ulonglong2*)&part2[kg][1][col0] = p;
            p.x = acc[2][1]; p.y = acc[3][1];
            *(ulonglong2*)&part2[kg][1][col0 + 2] = p;
        }
        __syncthreads();

        // ---- gates + state update: 8 warps, one batch each ----
        if (is_gate) {
            const unsigned long long* pb = &part2[0][gb][0];
            // reduce 4 kg-partials per gate column, packed, then lane-sum
            unsigned long long vr2 = f2add(f2add(pb[j],            pb[2*G3 + j]),
                                           f2add(pb[4*G3 + j],     pb[6*G3 + j]));
            unsigned long long vz2 = f2add(f2add(pb[128 + j],      pb[2*G3 + 128 + j]),
                                           f2add(pb[4*G3 + 128+j], pb[6*G3 + 128 + j]));
            unsigned long long vn2 = f2add(f2add(pb[256 + j],      pb[2*G3 + 256 + j]),
                                           f2add(pb[4*G3 + 256+j], pb[6*G3 + 256 + j]));
            float vr = psum2(vr2) + bhr;
            float vz = psum2(vz2) + bhz;
            float vn = psum2(vn2) + bhn;

            float rr = fast_sigmoid(xrc + vr);
            float zz = fast_sigmoid(xzc + vz);
            float nn = fast_tanh(xnc + rr * vn);
            float ho = h_sm[gb][j];
            float hn = nn + zz * (ho - nn);         // (1-z)n + z h
            h_sm[gb][j] = hn;
            out[((size_t)(b0 + gb) * SS + st) * HH + j] = hn;

            xrc = xrp; xzc = xzp; xnc = xnp;
        }
        __syncthreads();   // publish h for next step's matvec
    }

    // h_last
    if (t < HH) {
        const size_t off = (size_t)BB * SS * HH;
        out[off + (size_t)b0 * HH + t]       = h_sm[0][t];
        out[off + (size_t)(b0 + 1) * HH + t] = h_sm[1][t];
    }
}

// ---------------------------------------------------------------------------
extern "C" void kernel_launch(void* const* d_in, const int* in_sizes, int n_in,
                              void* d_out, int out_size) {
    (void)in_sizes; (void)n_in; (void)out_size;
    const float* X    = (const float*)d_in[0];   // inputs (B,S,I)
    const float* Win  = (const float*)d_in[1];   // W_in (I, 3H)
    const float* Wh   = (const float*)d_in[2];   // W_h  (H, 3H)
    const float* bias = (const float*)d_in[3];   // (6H,)
    float* out = (float*)d_out;

    cudaFuncSetAttribute(k_in_gemm,
                         cudaFuncAttributeMaxDynamicSharedMemorySize, SMEM_GEMM);

    k_in_gemm<<<(BB * SS) / 128, 256, SMEM_GEMM>>>(X, Win, bias);
    k_gru<<<BB / 2, 384>>>(Wh, bias, out);
}

// round 12
// speedup vs baseline: 1.1947x; 1.1067x over previous
#include <cuda_runtime.h>

// ManualGRU: B=256, S=2048, I=64, H=128
// out = [hidden_seq (B,S,H) fp32][h_last (B,H) fp32]

#define BB   256
#define SS   2048
#define II   64
#define HH   128
#define G3   384      // 3*H

// Scratch: from_input laid out as [s][b][384] so the scan reads coalesced rows.
__device__ float g_xin[(size_t)SS * BB * G3];

// ---------------- packed f32x2 helpers ----------------
__device__ __forceinline__ unsigned long long pk2(float lo, float hi) {
    unsigned long long r;
    asm("mov.b64 %0, {%1, %2};" : "=l"(r)
        : "r"(__float_as_uint(lo)), "r"(__float_as_uint(hi)));
    return r;
}
__device__ __forceinline__ unsigned long long f2fma(unsigned long long a,
                                                    unsigned long long b,
                                                    unsigned long long c) {
    unsigned long long d;
    asm("fma.rn.f32x2 %0, %1, %2, %3;" : "=l"(d) : "l"(a), "l"(b), "l"(c));
    return d;
}
__device__ __forceinline__ float psum2(unsigned long long p) {
    unsigned int lo, hi;
    asm("mov.b64 {%0, %1}, %2;" : "=r"(lo), "=r"(hi) : "l"(p));
    return __uint_as_float(lo) + __uint_as_float(hi);
}
__device__ __forceinline__ void unpk2(unsigned long long p, float& a, float& b) {
    unsigned int lo, hi;
    asm("mov.b64 {%0, %1}, %2;" : "=r"(lo), "=r"(hi) : "l"(p));
    a = __uint_as_float(lo); b = __uint_as_float(hi);
}

__device__ __forceinline__ float fast_sigmoid(float x) {
    float e = __expf(-x);
    return __fdividef(1.0f, 1.0f + e);
}
__device__ __forceinline__ float fast_tanh(float x) {
    float ax = fabsf(x);
    float e  = __expf(-2.0f * ax);
    float t  = __fdividef(1.0f - e, 1.0f + e);
    return copysignf(t, x);
}

// ---------------------------------------------------------------------------
// Phase 1: from_input = inputs @ W_in + b_in   (R10 version — measured ~545us)
// ---------------------------------------------------------------------------
#define AS2_STRIDE 65                    // u64 per row (64 + 1 pad)
#define SMEM_GEMM  (128 * AS2_STRIDE * 8 + 64 * 128 * 4)   // 99328 B

extern __shared__ unsigned long long dyn_smem[];

__global__ void __launch_bounds__(256, 2)
k_in_gemm(const float* __restrict__ X, const float* __restrict__ W,
          const float* __restrict__ bias) {
    unsigned long long* As2 = dyn_smem;                       // [128][65] u64 dup
    float*              Ws  = (float*)(dyn_smem + 128 * AS2_STRIDE); // [64][128]

    const int tid  = threadIdx.x;
    const int row0 = blockIdx.x * 128;
    const int bb   = row0 >> 11;
    const int s0   = row0 & 2047;

    {
        const float4* Xv = (const float4*)(X + (size_t)row0 * II);
#pragma unroll
        for (int i = 0; i < 8; i++) {
            int fi  = tid + 256 * i;
            float4 v = Xv[fi];
            int row = fi >> 4;
            int k4  = (fi & 15) * 4;
            unsigned long long* dst = &As2[row * AS2_STRIDE + k4];
            dst[0] = pk2(v.x, v.x);
            dst[1] = pk2(v.y, v.y);
            dst[2] = pk2(v.z, v.z);
            dst[3] = pk2(v.w, v.w);
        }
    }

    const int tx = tid & 15;
    const int ty = tid >> 4;

    for (int cc = 0; cc < 3; cc++) {
        __syncthreads();
#pragma unroll
        for (int i = 0; i < 8; i++) {
            int fi = tid + 256 * i;
            int k  = fi >> 5;
            int c  = (fi & 31) * 4;
            *(float4*)&Ws[k * 128 + c] =
                *(const float4*)&W[(size_t)k * G3 + cc * 128 + c];
        }
        __syncthreads();

        unsigned long long acc[8][4];
#pragma unroll
        for (int r = 0; r < 8; r++)
#pragma unroll
            for (int c = 0; c < 4; c++) acc[r][c] = 0ull;

#pragma unroll 8
        for (int k = 0; k < 64; k++) {
            ulonglong2 w01 = *(const ulonglong2*)&Ws[k * 128 + tx * 4];
            ulonglong2 w23 = *(const ulonglong2*)&Ws[k * 128 + 64 + tx * 4];
#pragma unroll
            for (int r = 0; r < 8; r++) {
                unsigned long long a = As2[(ty * 8 + r) * AS2_STRIDE + k];
                acc[r][0] = f2fma(a, w01.x, acc[r][0]);
                acc[r][1] = f2fma(a, w01.y, acc[r][1]);
                acc[r][2] = f2fma(a, w23.x, acc[r][2]);
                acc[r][3] = f2fma(a, w23.y, acc[r][3]);
            }
        }

        const int cb0 = cc * 128 + tx * 4;
        const int cb1 = cb0 + 64;
        const float4 bi0 = *(const float4*)&bias[cb0];
        const float4 bi1 = *(const float4*)&bias[cb1];
#pragma unroll
        for (int r = 0; r < 8; r++) {
            float4 o0, o1;
            unpk2(acc[r][0], o0.x, o0.y);
            unpk2(acc[r][1], o0.z, o0.w);
            unpk2(acc[r][2], o1.x, o1.y);
            unpk2(acc[r][3], o1.z, o1.w);
            o0.x += bi0.x; o0.y += bi0.y; o0.z += bi0.z; o0.w += bi0.w;
            o1.x += bi1.x; o1.y += bi1.y; o1.z += bi1.z; o1.w += bi1.w;
            int s = s0 + ty * 8 + r;
            float* orow = &g_xin[((size_t)s * BB + bb) * G3];
            *(float4*)&orow[cb0] = o0;
            *(float4*)&orow[cb1] = o1;
        }
    }
}

// ---------------------------------------------------------------------------
// Phase 2: GRU scan — R6 structure (float partials, psum in matvec) with the
// gate phase spread over 8 warps (one batch each) to halve its latency chain.
// 128 CTAs x 384 threads, 2 batches per CTA.
//   matvec: thread t: cg=t%96 owns cols 4cg..4cg+3, kg=t/96 owns k 32kg..+31
//   gates:  threads 128..255 -> batch 0, threads 256..383 -> batch 1, j=t&127
// ---------------------------------------------------------------------------
__global__ void __launch_bounds__(384, 1)
k_gru(const float* __restrict__ Wh, const float* __restrict__ bias,
      float* __restrict__ out) {
    __shared__ __align__(16) float h_sm[2][HH];        // 1 KB
    __shared__ __align__(16) float part[4][2][G3];     // 12 KB  [kg][b][col]

    const int t  = threadIdx.x;
    const int b0 = blockIdx.x * 2;
    const int cg = t % 96;
    const int kg = t / 96;            // 0..3 (uniform per warp)
    const int col0 = 4 * cg;
    const int k0   = 32 * kg;

    // Register-resident weights: wreg[c][i] = {Wh[k0+2i][col0+c], Wh[k0+2i+1][col0+c]}
    unsigned long long wreg[4][16];
#pragma unroll
    for (int i = 0; i < 16; i++) {
        const float* r0 = Wh + (size_t)(k0 + 2 * i) * G3 + col0;
        const float* r1 = r0 + G3;
#pragma unroll
        for (int c = 0; c < 4; c++) wreg[c][i] = pk2(r0[c], r1[c]);
    }

    // Gate-thread state: threads 128..383; gb = batch select, j = column
    const int is_gate = (t >= 128);
    const int gb = (t >= 256) ? 1 : 0;
    const int j  = t & 127;
    float bhr = 0.f, bhz = 0.f, bhn = 0.f;
    float xrc = 0.f, xzc = 0.f, xnc = 0.f;     // x(b0+gb, st) entering iter st
    if (is_gate) {
        bhr = bias[G3 + j];
        bhz = bias[G3 + 128 + j];
        bhn = bias[G3 + 256 + j];
        const float* xb = g_xin + (size_t)(b0 + gb) * G3;   // step 0
        xrc = xb[j]; xzc = xb[128 + j]; xnc = xb[256 + j];
    }

    if (t < HH) { h_sm[0][t] = 0.0f; h_sm[1][t] = 0.0f; }
    __syncthreads();

    for (int st = 0; st < SS; st++) {
        // Prefetch next step's x (gate threads only; consumed next iteration)
        float xrp = 0.f, xzp = 0.f, xnp = 0.f;
        if (is_gate && st + 1 < SS) {
            const float* xb = g_xin + ((size_t)(st + 1) * BB + b0 + gb) * G3;
            xrp = xb[j]; xzp = xb[128 + j]; xnp = xb[256 + j];
        }

        // ---- matvec partials: 4 cols x 2 batches over k-slice [k0,k0+32) ----
        unsigned long long acc[4][2];
#pragma unroll
        for (int c = 0; c < 4; c++) { acc[c][0] = 0ull; acc[c][1] = 0ull; }

        const ulonglong2* hv0 = (const ulonglong2*)&h_sm[0][k0];
        const ulonglong2* hv1 = (const ulonglong2*)&h_sm[1][k0];
#pragma unroll
        for (int q = 0; q < 8; q++) {
            ulonglong2 a = hv0[q];
            ulonglong2 b = hv1[q];
#pragma unroll
            for (int c = 0; c < 4; c++) {
                acc[c][0] = f2fma(wreg[c][2 * q],     a.x, acc[c][0]);
                acc[c][0] = f2fma(wreg[c][2 * q + 1], a.y, acc[c][0]);
                acc[c][1] = f2fma(wreg[c][2 * q],     b.x, acc[c][1]);
                acc[c][1] = f2fma(wreg[c][2 * q + 1], b.y, acc[c][1]);
            }
        }
        {
            float4 p0, p1;
            p0.x = psum2(acc[0][0]); p0.y = psum2(acc[1][0]);
            p0.z = psum2(acc[2][0]); p0.w = psum2(acc[3][0]);
            p1.x = psum2(acc[0][1]); p1.y = psum2(acc[1][1]);
            p1.z = psum2(acc[2][1]); p1.w = psum2(acc[3][1]);
            *(float4*)&part[kg][0][col0] = p0;
            *(float4*)&part[kg][1][col0] = p1;
        }
        __syncthreads();

        // ---- gates + state update: 8 warps, one batch per warp-group ----
        if (is_gate) {
            float vr = part[0][gb][j]       + part[1][gb][j]
                     + part[2][gb][j]       + part[3][gb][j]       + bhr;
            float vz = part[0][gb][128 + j] + part[1][gb][128 + j]
                     + part[2][gb][128 + j] + part[3][gb][128 + j] + bhz;
            float vn = part[0][gb][256 + j] + part[1][gb][256 + j]
                     + part[2][gb][256 + j] + part[3][gb][256 + j] + bhn;

            float rr = fast_sigmoid(xrc + vr);
            float zz = fast_sigmoid(xzc + vz);
            float nn = fast_tanh(xnc + rr * vn);
            float ho = h_sm[gb][j];
            float hn = nn + zz * (ho - nn);         // (1-z)n + z h
            h_sm[gb][j] = hn;
            out[((size_t)(b0 + gb) * SS + st) * HH + j] = hn;

            xrc = xrp; xzc = xzp; xnc = xnp;
        }
        __syncthreads();   // publish h for next step's matvec
    }

    // h_last
    if (t < HH) {
        const size_t off = (size_t)BB * SS * HH;
        out[off + (size_t)b0 * HH + t]       = h_sm[0][t];
        out[off + (size_t)(b0 + 1) * HH + t] = h_sm[1][t];
    }
}

// ---------------------------------------------------------------------------
extern "C" void kernel_launch(void* const* d_in, const int* in_sizes, int n_in,
                              void* d_out, int out_size) {
    (void)in_sizes; (void)n_in; (void)out_size;
    const float* X    = (const float*)d_in[0];   // inputs (B,S,I)
    const float* Win  = (const float*)d_in[1];   // W_in (I, 3H)
    const float* Wh   = (const float*)d_in[2];   // W_h  (H, 3H)
    const float* bias = (const float*)d_in[3];   // (6H,)
    float* out = (float*)d_out;

    cudaFuncSetAttribute(k_in_gemm,
                         cudaFuncAttributeMaxDynamicSharedMemorySize, SMEM_GEMM);

    k_in_gemm<<<(BB * SS) / 128, 256, SMEM_GEMM>>>(X, Win, bias);
    k_gru<<<BB / 2, 384>>>(Wh, bias, out);
}

// round 15
// speedup vs baseline: 1.3963x; 1.1687x over previous
#include <cuda_runtime.h>

// ManualGRU: B=256, S=2048, I=64, H=128
// out = [hidden_seq (B,S,H) fp32][h_last (B,H) fp32]
// Composition of measured bests: R9's k_gru (1.927 ms) + R10's k_in_gemm (~545 us)
// (Third submission — R13/R14 both died at GB300 container acquisition, before
//  any compile or run; no kernel-side evidence was produced.)

#define BB   256
#define SS   2048
#define II   64
#define HH   128
#define G3   384      // 3*H

// Scratch: from_input laid out as [s][b][384] so the scan reads coalesced rows.
__device__ float g_xin[(size_t)SS * BB * G3];

// ---------------- packed f32x2 helpers ----------------
__device__ __forceinline__ unsigned long long pk2(float lo, float hi) {
    unsigned long long r;
    asm("mov.b64 %0, {%1, %2};" : "=l"(r)
        : "r"(__float_as_uint(lo)), "r"(__float_as_uint(hi)));
    return r;
}
__device__ __forceinline__ unsigned long long f2fma(unsigned long long a,
                                                    unsigned long long b,
                                                    unsigned long long c) {
    unsigned long long d;
    asm("fma.rn.f32x2 %0, %1, %2, %3;" : "=l"(d) : "l"(a), "l"(b), "l"(c));
    return d;
}
__device__ __forceinline__ float psum2(unsigned long long p) {
    unsigned int lo, hi;
    asm("mov.b64 {%0, %1}, %2;" : "=r"(lo), "=r"(hi) : "l"(p));
    return __uint_as_float(lo) + __uint_as_float(hi);
}
__device__ __forceinline__ void unpk2(unsigned long long p, float& a, float& b) {
    unsigned int lo, hi;
    asm("mov.b64 {%0, %1}, %2;" : "=r"(lo), "=r"(hi) : "l"(p));
    a = __uint_as_float(lo); b = __uint_as_float(hi);
}

__device__ __forceinline__ float fast_sigmoid(float x) {
    float e = __expf(-x);
    return __fdividef(1.0f, 1.0f + e);
}
__device__ __forceinline__ float fast_tanh(float x) {
    float ax = fabsf(x);
    float e  = __expf(-2.0f * ax);
    float t  = __fdividef(1.0f - e, 1.0f + e);
    return copysignf(t, x);
}

// ---------------------------------------------------------------------------
// Phase 1: from_input = inputs @ W_in + b_in   (R10 version — measured ~545us)
// 128 rows/block, 3 col-chunks of 128, 256 threads, 8x8 thread tiles.
// A tile stored pre-duplicated as f32x2 (u64), padded stride -> LDS.64
// broadcast, zero pack movs. W chunk read as LDS.128 col-pairs.
// ---------------------------------------------------------------------------
#define AS2_STRIDE 65                    // u64 per row (64 + 1 pad)
#define SMEM_GEMM  (128 * AS2_STRIDE * 8 + 64 * 128 * 4)   // 99328 B

extern __shared__ unsigned long long dyn_smem[];

__global__ void __launch_bounds__(256, 2)
k_in_gemm(const float* __restrict__ X, const float* __restrict__ W,
          const float* __restrict__ bias) {
    unsigned long long* As2 = dyn_smem;                       // [128][65] u64 dup
    float*              Ws  = (float*)(dyn_smem + 128 * AS2_STRIDE); // [64][128]

    const int tid  = threadIdx.x;
    const int row0 = blockIdx.x * 128;
    const int bb   = row0 >> 11;
    const int s0   = row0 & 2047;

    {
        const float4* Xv = (const float4*)(X + (size_t)row0 * II);
#pragma unroll
        for (int i = 0; i < 8; i++) {
            int fi  = tid + 256 * i;
            float4 v = Xv[fi];
            int row = fi >> 4;
            int k4  = (fi & 15) * 4;
            unsigned long long* dst = &As2[row * AS2_STRIDE + k4];
            dst[0] = pk2(v.x, v.x);
            dst[1] = pk2(v.y, v.y);
            dst[2] = pk2(v.z, v.z);
            dst[3] = pk2(v.w, v.w);
        }
    }

    const int tx = tid & 15;
    const int ty = tid >> 4;

    for (int cc = 0; cc < 3; cc++) {
        __syncthreads();
#pragma unroll
        for (int i = 0; i < 8; i++) {
            int fi = tid + 256 * i;
            int k  = fi >> 5;
            int c  = (fi & 31) * 4;
            *(float4*)&Ws[k * 128 + c] =
                *(const float4*)&W[(size_t)k * G3 + cc * 128 + c];
        }
        __syncthreads();

        unsigned long long acc[8][4];
#pragma unroll
        for (int r = 0; r < 8; r++)
#pragma unroll
            for (int c = 0; c < 4; c++) acc[r][c] = 0ull;

#pragma unroll 8
        for (int k = 0; k < 64; k++) {
            ulonglong2 w01 = *(const ulonglong2*)&Ws[k * 128 + tx * 4];
            ulonglong2 w23 = *(const ulonglong2*)&Ws[k * 128 + 64 + tx * 4];
#pragma unroll
            for (int r = 0; r < 8; r++) {
                unsigned long long a = As2[(ty * 8 + r) * AS2_STRIDE + k];
                acc[r][0] = f2fma(a, w01.x, acc[r][0]);
                acc[r][1] = f2fma(a, w01.y, acc[r][1]);
                acc[r][2] = f2fma(a, w23.x, acc[r][2]);
                acc[r][3] = f2fma(a, w23.y, acc[r][3]);
            }
        }

        const int cb0 = cc * 128 + tx * 4;
        const int cb1 = cb0 + 64;
        const float4 bi0 = *(const float4*)&bias[cb0];
        const float4 bi1 = *(const float4*)&bias[cb1];
#pragma unroll
        for (int r = 0; r < 8; r++) {
            float4 o0, o1;
            unpk2(acc[r][0], o0.x, o0.y);
            unpk2(acc[r][1], o0.z, o0.w);
            unpk2(acc[r][2], o1.x, o1.y);
            unpk2(acc[r][3], o1.z, o1.w);
            o0.x += bi0.x; o0.y += bi0.y; o0.z += bi0.z; o0.w += bi0.w;
            o1.x += bi1.x; o1.y += bi1.y; o1.z += bi1.z; o1.w += bi1.w;
            int s = s0 + ty * 8 + r;
            float* orow = &g_xin[((size_t)s * BB + bb) * G3];
            *(float4*)&orow[cb0] = o0;
            *(float4*)&orow[cb1] = o1;
        }
    }
}

// ---------------------------------------------------------------------------
// Phase 2: GRU scan — EXACT R9 structure (measured 1.927 ms).
// 128 CTAs x 384 threads, 2 batches per CTA, k-split matvec:
//   thread t: cg=t%96 owns cols 4cg..4cg+3, kg=t/96 owns k-slice 32kg..32kg+31
// Gates + state update in threads 256..383 (j = t-256), 2 batches per thread.
// ---------------------------------------------------------------------------
__global__ void __launch_bounds__(384, 1)
k_gru(const float* __restrict__ Wh, const float* __restrict__ bias,
      float* __restrict__ out) {
    __shared__ __align__(16) float h_sm[2][HH];        // 1 KB
    __shared__ __align__(16) float part[4][2][G3];     // 12 KB  [kg][b][col]

    const int t  = threadIdx.x;
    const int b0 = blockIdx.x * 2;
    const int cg = t % 96;
    const int kg = t / 96;            // 0..3 (uniform per warp)
    const int col0 = 4 * cg;
    const int k0   = 32 * kg;

    // Register-resident weights: wreg[c][i] = {Wh[k0+2i][col0+c], Wh[k0+2i+1][col0+c]}
    unsigned long long wreg[4][16];
#pragma unroll
    for (int i = 0; i < 16; i++) {
        const float* r0 = Wh + (size_t)(k0 + 2 * i) * G3 + col0;
        const float* r1 = r0 + G3;
#pragma unroll
        for (int c = 0; c < 4; c++) wreg[c][i] = pk2(r0[c], r1[c]);
    }

    // Gate-thread state (threads 256..383, j = t-256)
    const int j = t - 256;
    float bhr = 0.f, bhz = 0.f, bhn = 0.f;
    float xr0c = 0.f, xz0c = 0.f, xn0c = 0.f, xr1c = 0.f, xz1c = 0.f, xn1c = 0.f;
    if (t >= 256) {
        bhr = bias[G3 + j];
        bhz = bias[G3 + 128 + j];
        bhn = bias[G3 + 256 + j];
        const float* xb = g_xin + (size_t)(0 * BB + b0) * G3;
        xr0c = xb[j];        xz0c = xb[128 + j];        xn0c = xb[256 + j];
        xr1c = xb[G3 + j];   xz1c = xb[G3 + 128 + j];   xn1c = xb[G3 + 256 + j];
    }

    if (t < HH) { h_sm[0][t] = 0.0f; h_sm[1][t] = 0.0f; }
    __syncthreads();

    for (int st = 0; st < SS; st++) {
        // Prefetch next step's x (gate threads only)
        float xr0p = 0.f, xz0p = 0.f, xn0p = 0.f, xr1p = 0.f, xz1p = 0.f, xn1p = 0.f;
        if (t >= 256 && st + 1 < SS) {
            const float* xb = g_xin + (size_t)((st + 1) * BB + b0) * G3;
            xr0p = xb[j];        xz0p = xb[128 + j];        xn0p = xb[256 + j];
            xr1p = xb[G3 + j];   xz1p = xb[G3 + 128 + j];   xn1p = xb[G3 + 256 + j];
        }

        // ---- matvec partials: 4 cols x 2 batches over k-slice [k0, k0+32) ----
        unsigned long long acc[4][2];
#pragma unroll
        for (int c = 0; c < 4; c++) { acc[c][0] = 0ull; acc[c][1] = 0ull; }

        const ulonglong2* hv0 = (const ulonglong2*)&h_sm[0][k0];  // 8 x 16B
        const ulonglong2* hv1 = (const ulonglong2*)&h_sm[1][k0];
#pragma unroll
        for (int q = 0; q < 8; q++) {
            ulonglong2 a = hv0[q];
            ulonglong2 b = hv1[q];
#pragma unroll
            for (int c = 0; c < 4; c++) {
                acc[c][0] = f2fma(wreg[c][2 * q],     a.x, acc[c][0]);
                acc[c][0] = f2fma(wreg[c][2 * q + 1], a.y, acc[c][0]);
                acc[c][1] = f2fma(wreg[c][2 * q],     b.x, acc[c][1]);
                acc[c][1] = f2fma(wreg[c][2 * q + 1], b.y, acc[c][1]);
            }
        }

        {
            float4 p0, p1;
            p0.x = psum2(acc[0][0]); p0.y = psum2(acc[1][0]);
            p0.z = psum2(acc[2][0]); p0.w = psum2(acc[3][0]);
            p1.x = psum2(acc[0][1]); p1.y = psum2(acc[1][1]);
            p1.z = psum2(acc[2][1]); p1.w = psum2(acc[3][1]);
            *(float4*)&part[kg][0][col0] = p0;
            *(float4*)&part[kg][1][col0] = p1;
        }
        __syncthreads();

        // ---- gates + state update: threads 256..383 (j = t-256) ----
        if (t >= 256) {
            // batch 0
            float vr0 = part[0][0][j] + part[1][0][j] + part[2][0][j] + part[3][0][j] + bhr;
            float vz0 = part[0][0][128 + j] + part[1][0][128 + j]
                      + part[2][0][128 + j] + part[3][0][128 + j] + bhz;
            float vn0 = part[0][0][256 + j] + part[1][0][256 + j]
                      + part[2][0][256 + j] + part[3][0][256 + j] + bhn;
            // batch 1
            float vr1 = part[0][1][j] + part[1][1][j] + part[2][1][j] + part[3][1][j] + bhr;
            float vz1 = part[0][1][128 + j] + part[1][1][128 + j]
                      + part[2][1][128 + j] + part[3][1][128 + j] + bhz;
            float vn1 = part[0][1][256 + j] + part[1][1][256 + j]
                      + part[2][1][256 + j] + part[3][1][256 + j] + bhn;

            float r0 = fast_sigmoid(xr0c + vr0);
            float z0 = fast_sigmoid(xz0c + vz0);
            float r1 = fast_sigmoid(xr1c + vr1);
            float z1 = fast_sigmoid(xz1c + vz1);

            float n0 = fast_tanh(xn0c + r0 * vn0);
            float n1 = fast_tanh(xn1c + r1 * vn1);

            float ho0 = h_sm[0][j];
            float ho1 = h_sm[1][j];
            float hn0 = n0 + z0 * (ho0 - n0);       // (1-z)n + z h
            float hn1 = n1 + z1 * (ho1 - n1);
            h_sm[0][j] = hn0;
            h_sm[1][j] = hn1;
            out[((size_t)b0 * SS + st) * HH + j]       = hn0;
            out[((size_t)(b0 + 1) * SS + st) * HH + j] = hn1;

            xr0c = xr0p; xz0c = xz0p; xn0c = xn0p;
            xr1c = xr1p; xz1c = xz1p; xn1c = xn1p;
        }
        __syncthreads();   // publish h for next step's matvec
    }

    // h_last
    if (t < HH) {
        const size_t off = (size_t)BB * SS * HH;
        out[off + (size_t)b0 * HH + t]       = h_sm[0][t];
        out[off + (size_t)(b0 + 1) * HH + t] = h_sm[1][t];
    }
}

// ---------------------------------------------------------------------------
extern "C" void kernel_launch(void* const* d_in, const int* in_sizes, int n_in,
                              void* d_out, int out_size) {
    (void)in_sizes; (void)n_in; (void)out_size;
    const float* X    = (const float*)d_in[0];   // inputs (B,S,I)
    const float* Win  = (const float*)d_in[1];   // W_in (I, 3H)
    const float* Wh   = (const float*)d_in[2];   // W_h  (H, 3H)
    const float* bias = (const float*)d_in[3];   // (6H,)
    float* out = (float*)d_out;

    cudaFuncSetAttribute(k_in_gemm,
                         cudaFuncAttributeMaxDynamicSharedMemorySize, SMEM_GEMM);

    k_in_gemm<<<(BB * SS) / 128, 256, SMEM_GEMM>>>(X, Win, bias);
    k_gru<<<BB / 2, 384>>>(Wh, bias, out);
}